// round 14
// baseline (speedup 1.0000x reference)
#include <cuda_runtime.h>
#include <cuda_bf16.h>
#include <math.h>
#include <float.h>

#define An    8
#define Bn    4096
#define FEATn 2560
#define SQRTD 11.3137085f

typedef unsigned long long u64;

// ------------- static device scratch (no allocation) -------------
__device__ __align__(16) float g_M1Pf[128 * 256];   // [kp][c*2+par] paired M1
__device__ __align__(16) float g_WencPf[32 * 512];  // [kp][c*2+par] paired Wenc
__device__ __align__(16) float g_M2P[128 * 128];    // [ep][hp*2+par]
__device__ __align__(16) float2 g_WvP[32 * 256];    // [kp][c]
__device__ float g_logit1[16 * Bn * 7];
__device__ float g_psum1[16 * 8];    // stage-1 mean partials
__device__ float g_lp[16 * Bn * 64];
__device__ float g_psum2[16 * 32];   // stage-2 mean partials
__device__ float g_pmax[16 * 32 * 64];
__device__ int   g_pargb[16 * 32 * 64];
__device__ float g_cargoT[(size_t)Bn * 2048];

__device__ __forceinline__ void ffma2(u64& acc, u64 x, u64 w) {
    asm("fma.rn.f32x2 %0, %1, %2, %0;" : "+l"(acc) : "l"(x), "l"(w));
}
__device__ __forceinline__ float2 unpack2(u64 v) {
    float2 f; asm("mov.b64 {%0, %1}, %2;" : "=f"(f.x), "=f"(f.y) : "l"(v)); return f;
}

// ---------------- K0: all prep, weight blocks FIRST, cargo after --------------
// blocks [0,128): M1 paired | [128,288): M2P/WvP/WencP | [288,4384): cargo b
__global__ void k0_all(const float* __restrict__ obs,
                       const float* __restrict__ Wsel_nb, const float* __restrict__ Wk_nb,
                       const float* __restrict__ Wsel_poi, const float* __restrict__ Wk_poi,
                       const float* __restrict__ Wv, const float* __restrict__ Wenc) {
    __shared__ float T[32 * 65];
    int tid = threadIdx.x;
    if (blockIdx.x < 128) {
        int idx = blockIdx.x * 256 + tid;  // e(256) x ho(128)
        int e = idx >> 7, ho = idx & 127;
        int h = ho >> 6, o = ho & 63;
        const float* ws = Wsel_nb + h * 32768;
        const float* wk = Wk_nb + h * 8192;
        float s = 0.f;
        for (int d = 0; d < 128; d++) s += ws[d * 256 + e] * wk[d * 64 + o];
        g_M1Pf[(e >> 1) * 256 + ho * 2 + (e & 1)] = s;
        return;
    }
    if (blockIdx.x < 288) {
        int idx = (blockIdx.x - 128) * 256 + tid;
        if (idx < 16384) {
            int e = idx >> 6, hp = idx & 63;
            int h = hp >> 5, p = hp & 31;
            const float* ws = Wsel_poi + h * 32768;
            const float* wk = Wk_poi + h * 4096;
            float s = 0.f;
            for (int d = 0; d < 128; d++) s += ws[d * 256 + e] * wk[d * 32 + p];
            g_M2P[(e >> 1) * 128 + hp * 2 + (e & 1)] = s;
        } else if (idx < 24576) {
            int i3 = idx - 16384;
            int kp = i3 >> 8, c = i3 & 255;
            g_WvP[i3] = make_float2(Wv[c * 64 + 2 * kp], Wv[c * 64 + 2 * kp + 1]);
        } else {
            int i4 = idx - 24576;  // [kp(32)][c(256)][par(2)]
            int kp = i4 >> 9, rest = i4 & 511, c = rest >> 1, par = rest & 1;
            g_WencPf[i4] = Wenc[c * 64 + 2 * kp + par];
        }
        return;
    }
    int b = blockIdx.x - 288;
    const float4* in = (const float4*)(obs + (size_t)b * FEATn + 512);
    for (int i = tid; i < 512; i += 256) {
        float4 v = in[i];
        int c = i >> 3, p0 = (i & 7) * 4;
        T[(p0 + 0) * 65 + c] = v.x;
        T[(p0 + 1) * 65 + c] = v.y;
        T[(p0 + 2) * 65 + c] = v.z;
        T[(p0 + 3) * 65 + c] = v.w;
    }
    __syncthreads();
    float* ob = g_cargoT + (size_t)b * 2048;
    for (int i = tid; i < 2048; i += 256) ob[i] = T[(i >> 6) * 65 + (i & 63)];
}

// ---------------- K1: enc -> u -> stage-1 logits (shfl scheme, 32 rows) -------
__global__ __launch_bounds__(256, 2)
void k1_stage1(const float* __restrict__ obs, const float* __restrict__ benc) {
    extern __shared__ float F[];
    float* Fself = F;
    float* Fenc = F + 2176;
    float* Fu = F + 10496;
    const int a = blockIdx.y, b0 = blockIdx.x * 32, tid = threadIdx.x;
    const int lane = tid & 31;
    const int colT = tid & 63, rowT = tid >> 6;

    for (int i = tid; i < 512; i += 256) {
        int r = i >> 4, q4 = (i & 15) * 4;
        *(float4*)(Fself + r * 68 + q4) =
            *(const float4*)(obs + ((size_t)a * Bn + b0 + r) * FEATn + 448 + q4);
    }
    float breg[4];
#pragma unroll
    for (int c = 0; c < 4; c++) breg[c] = benc[colT * 4 + c];
    __syncthreads();

    {
        u64 acc2[8][4];
#pragma unroll
        for (int r = 0; r < 8; r++)
#pragma unroll
            for (int c = 0; c < 4; c++) acc2[r][c] = 0ull;
#pragma unroll 4
        for (int kp = 0; kp < 32; kp++) {
            u64 tmp = 0ull;
            if (lane < 8) tmp = *(const u64*)&Fself[(rowT * 8 + lane) * 68 + 2 * kp];
            ulonglong2 wA = *(const ulonglong2*)&g_WencPf[kp * 512 + colT * 8];
            ulonglong2 wB = *(const ulonglong2*)&g_WencPf[kp * 512 + colT * 8 + 4];
#pragma unroll
            for (int r = 0; r < 8; r++) {
                u64 xv = __shfl_sync(0xffffffffu, tmp, r);
                ffma2(acc2[r][0], xv, wA.x);
                ffma2(acc2[r][1], xv, wA.y);
                ffma2(acc2[r][2], xv, wB.x);
                ffma2(acc2[r][3], xv, wB.y);
            }
        }
#pragma unroll
        for (int r = 0; r < 8; r++)
#pragma unroll
            for (int c = 0; c < 4; c++) {
                float2 f = unpack2(acc2[r][c]);
                float v = f.x + f.y + breg[c];
                Fenc[(rowT * 8 + r) * 260 + colT * 4 + c] = (v >= 0.f) ? v : 0.01f * v;
            }
    }
    __syncthreads();

    {
        u64 uacc[8][2];
#pragma unroll
        for (int r = 0; r < 8; r++) { uacc[r][0] = 0ull; uacc[r][1] = 0ull; }
#pragma unroll 4
        for (int kp = 0; kp < 128; kp++) {
            u64 tmp = 0ull;
            if (lane < 8) tmp = *(const u64*)&Fenc[(rowT * 8 + lane) * 260 + 2 * kp];
            ulonglong2 m = *(const ulonglong2*)&g_M1Pf[kp * 256 + colT * 4];
#pragma unroll
            for (int r = 0; r < 8; r++) {
                u64 xv = __shfl_sync(0xffffffffu, tmp, r);
                ffma2(uacc[r][0], xv, m.x);
                ffma2(uacc[r][1], xv, m.y);
            }
        }
#pragma unroll
        for (int r = 0; r < 8; r++) {
            float2 fa = unpack2(uacc[r][0]), fb = unpack2(uacc[r][1]);
            Fu[(rowT * 8 + r) * 132 + colT * 2] = fa.x + fa.y;
            Fu[(rowT * 8 + r) * 132 + colT * 2 + 1] = fb.x + fb.y;
        }
    }
    __syncthreads();

    {
        int w = tid >> 5;
        for (int rr = 0; rr < 4; rr++) {
            int r = w * 4 + rr, b = b0 + r;
            float u0 = Fu[r * 132 + lane], u1 = Fu[r * 132 + 32 + lane];
            float u2 = Fu[r * 132 + 64 + lane], u3 = Fu[r * 132 + 96 + lane];
            const float* x = obs + ((size_t)a * Bn + b) * FEATn;
#pragma unroll
            for (int n = 0; n < 7; n++) {
                float xa = x[n * 64 + lane], xb = x[n * 64 + 32 + lane];
                float p0 = xa * u0 + xb * u1;
                float p1 = xa * u2 + xb * u3;
#pragma unroll
                for (int off = 16; off; off >>= 1) {
                    p0 += __shfl_xor_sync(0xffffffffu, p0, off);
                    p1 += __shfl_xor_sync(0xffffffffu, p1, off);
                }
                if (lane == 0) {
                    g_logit1[((size_t)a * Bn + b) * 7 + n] = p0 / SQRTD;
                    g_logit1[((size_t)(8 + a) * Bn + b) * 7 + n] = p1 / SQRTD;
                }
            }
        }
    }
}

// ---------------- K2a: stage-1 mean partials, grid (16,8) --------------------
__global__ void k2a_partial() {
    int pair = blockIdx.x, chunk = blockIdx.y;
    const float* p = g_logit1 + (size_t)pair * Bn * 7 + chunk * 3584;
    float s = 0.f;
    for (int i = threadIdx.x; i < 3584; i += 256) s += p[i];
    __shared__ float red[256];
    red[threadIdx.x] = s;
    __syncthreads();
    for (int st = 128; st; st >>= 1) {
        if (threadIdx.x < st) red[threadIdx.x] += red[threadIdx.x + st];
        __syncthreads();
    }
    if (threadIdx.x == 0) g_psum1[pair * 8 + chunk] = red[0];
}

// ---------------- K3: V-GEMM (shfl, reg accum), t, lp ------------------------
__global__ __launch_bounds__(256, 2)
void k3_stage2(const float* __restrict__ obs, const float* __restrict__ bv) {
    extern __shared__ float F[];
    float* Fwv = F;
    float* Fnbacc = F + 16384;
    float* Fx = F + 24704;
    float* Fw = F + 26880;
    float* Ft = Fx;
    const int a = blockIdx.y, b0 = blockIdx.x * 32, tid = threadIdx.x;
    const int lane = tid & 31;

    {
        const float4* src = (const float4*)g_WvP;
        float4* dst = (float4*)Fwv;
        for (int i = tid; i < 4096; i += 256) dst[i] = src[i];
    }
    if (tid < 64) {
        int r = tid >> 1, h2 = tid & 1, pair = h2 * 8 + a, b = b0 + r;
        float dn = 0.f;
#pragma unroll
        for (int j = 0; j < 8; j++) dn += g_psum1[pair * 8 + j];
        dn = dn / 28672.0f + 1e-9f;
        const float* lg = g_logit1 + ((size_t)pair * Bn + b) * 7;
        float L[7], m = -FLT_MAX, s = 0.f;
#pragma unroll
        for (int n = 0; n < 7; n++) { L[n] = lg[n] / dn; m = fmaxf(m, L[n]); }
#pragma unroll
        for (int n = 0; n < 7; n++) { L[n] = expf(L[n] - m); s += L[n]; }
#pragma unroll
        for (int n = 0; n < 7; n++) Fw[r * 16 + h2 * 8 + n] = L[n] / s;
    }

    const int colT = tid & 63, rowT = tid >> 6;
    const int h = (tid >> 5) & 1;
    float bvr[4];
#pragma unroll
    for (int c = 0; c < 4; c++) bvr[c] = bv[colT * 4 + c];

    float nbacc[8][4];
#pragma unroll
    for (int r = 0; r < 8; r++)
#pragma unroll
        for (int c = 0; c < 4; c++) nbacc[r][c] = 0.f;

    for (int n = 0; n < 7; n++) {
        __syncthreads();
        for (int i = tid; i < 512; i += 256) {
            int r = i >> 4, q4 = (i & 15) * 4;
            *(float4*)(Fx + r * 68 + q4) =
                *(const float4*)(obs + ((size_t)a * Bn + b0 + r) * FEATn + n * 64 + q4);
        }
        __syncthreads();

        u64 acc2[8][4];
#pragma unroll
        for (int r = 0; r < 8; r++)
#pragma unroll
            for (int c = 0; c < 4; c++) acc2[r][c] = 0ull;

#pragma unroll 4
        for (int kp = 0; kp < 32; kp++) {
            u64 tmp = 0ull;
            if (lane < 8) tmp = *(const u64*)&Fx[(rowT * 8 + lane) * 68 + 2 * kp];
            ulonglong2 wA = *(const ulonglong2*)&Fwv[kp * 512 + colT * 8];
            ulonglong2 wB = *(const ulonglong2*)&Fwv[kp * 512 + colT * 8 + 4];
#pragma unroll
            for (int r = 0; r < 8; r++) {
                u64 xv = __shfl_sync(0xffffffffu, tmp, r);
                ffma2(acc2[r][0], xv, wA.x);
                ffma2(acc2[r][1], xv, wA.y);
                ffma2(acc2[r][2], xv, wB.x);
                ffma2(acc2[r][3], xv, wB.y);
            }
        }
#pragma unroll
        for (int r = 0; r < 8; r++) {
            float wr = Fw[(rowT * 8 + r) * 16 + h * 8 + n];
            float2 f0 = unpack2(acc2[r][0]), f1 = unpack2(acc2[r][1]);
            float2 f2 = unpack2(acc2[r][2]), f3 = unpack2(acc2[r][3]);
            float v0 = f0.x + f0.y + bvr[0]; v0 = (v0 >= 0.f) ? v0 : 0.01f * v0;
            float v1 = f1.x + f1.y + bvr[1]; v1 = (v1 >= 0.f) ? v1 : 0.01f * v1;
            float v2 = f2.x + f2.y + bvr[2]; v2 = (v2 >= 0.f) ? v2 : 0.01f * v2;
            float v3 = f3.x + f3.y + bvr[3]; v3 = (v3 >= 0.f) ? v3 : 0.01f * v3;
            nbacc[r][0] += wr * v0; nbacc[r][1] += wr * v1;
            nbacc[r][2] += wr * v2; nbacc[r][3] += wr * v3;
        }
    }
    __syncthreads();
#pragma unroll
    for (int r = 0; r < 8; r++)
        *(float4*)&Fnbacc[(rowT * 8 + r) * 260 + colT * 4] =
            make_float4(nbacc[r][0], nbacc[r][1], nbacc[r][2], nbacc[r][3]);
    __syncthreads();

    {
        const int colTt = tid & 31, rowTt = tid >> 5;
        u64 tacc[4][2];
#pragma unroll
        for (int r = 0; r < 4; r++) { tacc[r][0] = 0ull; tacc[r][1] = 0ull; }
#pragma unroll 4
        for (int ep = 0; ep < 128; ep++) {
            u64 tmp = 0ull;
            if (lane < 4) tmp = *(const u64*)&Fnbacc[(rowTt * 4 + lane) * 260 + 2 * ep];
            ulonglong2 m2 = *(const ulonglong2*)&g_M2P[ep * 128 + colTt * 4];
#pragma unroll
            for (int r = 0; r < 4; r++) {
                u64 xv = __shfl_sync(0xffffffffu, tmp, r);
                ffma2(tacc[r][0], xv, m2.x);
                ffma2(tacc[r][1], xv, m2.y);
            }
        }
        __syncthreads();
#pragma unroll
        for (int r = 0; r < 4; r++) {
            float2 fa = unpack2(tacc[r][0]), fb = unpack2(tacc[r][1]);
            Ft[(rowTt * 4 + r) * 64 + colTt * 2] = (fa.x + fa.y) * (1.0f / SQRTD);
            Ft[(rowTt * 4 + r) * 64 + colTt * 2 + 1] = (fb.x + fb.y) * (1.0f / SQRTD);
        }
    }
    __syncthreads();

    {
        int w8 = tid >> 5;
        for (int rr = 0; rr < 4; rr++) {
            int r = w8 * 4 + rr, b = b0 + r;
            const float* ct = g_cargoT + (size_t)b * 2048;
#pragma unroll
            for (int ch = 0; ch < 2; ch++) {
                float acc0 = 0.f, acc1 = 0.f;
#pragma unroll
                for (int p = 0; p < 32; p++) {
                    float x = ct[p * 64 + ch * 32 + lane];
                    acc0 = fmaf(Ft[r * 64 + p], x, acc0);
                    acc1 = fmaf(Ft[r * 64 + 32 + p], x, acc1);
                }
                g_lp[((size_t)a * Bn + b) * 64 + ch * 32 + lane] = acc0;
                g_lp[((size_t)(8 + a) * Bn + b) * 64 + ch * 32 + lane] = acc1;
            }
        }
    }
}

// ---------------- K4a: stage-2 mean partials, grid (16,32) --------------------
__global__ void k4a_partial() {
    int pair = blockIdx.x, chunk = blockIdx.y;
    const float* p = g_lp + (size_t)pair * Bn * 64 + chunk * 8192;
    float s = 0.f;
    for (int i = threadIdx.x; i < 8192; i += 256) s += p[i];
    __shared__ float red[256];
    red[threadIdx.x] = s;
    __syncthreads();
    for (int st = 128; st; st >>= 1) {
        if (threadIdx.x < st) red[threadIdx.x] += red[threadIdx.x + st];
        __syncthreads();
    }
    if (threadIdx.x == 0) g_psum2[pair * 32 + chunk] = red[0];
}

// ---------------- K5: fused softmax + column (max, first-b) stats ------------
__global__ void k5_stats() {
    int pair = blockIdx.x, chunk = blockIdx.y;
    int w = threadIdx.x >> 5, lane = threadIdx.x & 31;
    float d = 0.f;
#pragma unroll
    for (int j = 0; j < 32; j++) d += g_psum2[pair * 32 + j];
    d = d / 262144.0f + 1e-9f;
    float m0 = -FLT_MAX, m1 = -FLT_MAX;
    int a0 = 1 << 30, a1 = 1 << 30;
    int brow0 = chunk * 128 + w * 16;
    for (int i = 0; i < 16; i++) {
        int b = brow0 + i;
        const float* p = g_lp + ((size_t)pair * Bn + b) * 64;
        float L0 = p[lane] / d, L1 = p[lane + 32] / d;
        float mx = fmaxf(L0, L1);
#pragma unroll
        for (int off = 16; off; off >>= 1) mx = fmaxf(mx, __shfl_xor_sync(0xffffffffu, mx, off));
        float e0 = expf(L0 - mx), e1 = expf(L1 - mx);
        float s = e0 + e1;
#pragma unroll
        for (int off = 16; off; off >>= 1) s += __shfl_xor_sync(0xffffffffu, s, off);
        float inv = 1.0f / s;
        float w0 = e0 * inv, w1 = e1 * inv;
        if (w0 > m0) { m0 = w0; a0 = b; }
        if (w1 > m1) { m1 = w1; a1 = b; }
    }
    __shared__ float sv[8 * 64];
    __shared__ int sb[8 * 64];
    sv[w * 64 + lane] = m0;        sb[w * 64 + lane] = a0;
    sv[w * 64 + lane + 32] = m1;   sb[w * 64 + lane + 32] = a1;
    __syncthreads();
    if (threadIdx.x < 64) {
        int c = threadIdx.x;
        float bvv = sv[c];
        int bbb = sb[c];
        for (int j = 1; j < 8; j++) {
            float v2 = sv[j * 64 + c];
            int b2 = sb[j * 64 + c];
            if (v2 > bvv || (v2 == bvv && b2 < bbb)) { bvv = v2; bbb = b2; }
        }
        g_pmax[(pair * 32 + chunk) * 64 + c] = bvv;
        g_pargb[(pair * 32 + chunk) * 64 + c] = bbb;
    }
}

// ---------------- K6: merge stats, 16-step scan, broadcast output ------------
__global__ void k6_scan(const float* __restrict__ obs, float* __restrict__ out) {
    __shared__ float smax[1024];
    __shared__ int sab[1024];
    __shared__ int smask[64];
    __shared__ float sci[8];
    int tid = threadIdx.x;
    for (int i = tid; i < 1024; i += 256) {
        int pair = i >> 6, c = i & 63;
        float bvv = -FLT_MAX;
        int bbb = 1 << 30;
        for (int j = 0; j < 32; j++) {
            float v = g_pmax[(pair * 32 + j) * 64 + c];
            int b2 = g_pargb[(pair * 32 + j) * 64 + c];
            if (v > bvv || (v == bvv && b2 < bbb)) { bvv = v; bbb = b2; }
        }
        smax[i] = bvv;
        sab[i] = bbb;
    }
    if (tid < 64) {
        int off = (32 * tid + 2047) & 2047;
        smask[tid] = (obs[512 + off] == 1.0f) ? 1 : 0;
    }
    __syncthreads();
    if (tid == 0) {
        for (int i = 0; i < 16; i++) {
            float bestv = -FLT_MAX;
            int bestflat = -1;
            for (int c = 0; c < 64; c++) {
                if (smask[c]) continue;
                float v = smax[i * 64 + c];
                int flat = sab[i * 64 + c] * 64 + c;
                if (bestflat < 0 || v > bestv || (v == bestv && flat < bestflat)) {
                    bestv = v;
                    bestflat = flat;
                }
            }
            int ci = (bestflat < 0) ? 0 : bestflat;
            if (ci < 64) smask[ci] = 1;
            if (i >= 8) sci[i - 8] = (float)ci;
        }
    }
    __syncthreads();
    for (int i = tid; i < 32768; i += 256) out[i] = sci[i >> 12];
}

extern "C" void kernel_launch(void* const* d_in, const int* in_sizes, int n_in,
                              void* d_out, int out_size) {
    const float* obs = (const float*)d_in[0];
    const float* Wenc = (const float*)d_in[1];
    const float* benc = (const float*)d_in[2];
    const float* Wk_nb = (const float*)d_in[3];
    const float* Wsel_nb = (const float*)d_in[4];
    const float* Wv_nb = (const float*)d_in[5];
    const float* bv_nb = (const float*)d_in[6];
    const float* Wk_poi = (const float*)d_in[7];
    const float* Wsel_poi = (const float*)d_in[8];
    float* out = (float*)d_out;

    cudaFuncSetAttribute(k1_stage1, cudaFuncAttributeMaxDynamicSharedMemorySize, 58880);
    cudaFuncSetAttribute(k3_stage2, cudaFuncAttributeMaxDynamicSharedMemorySize, 109568);

    k0_all<<<4384, 256>>>(obs, Wsel_nb, Wk_nb, Wsel_poi, Wk_poi, Wv_nb, Wenc);
    k1_stage1<<<dim3(128, 8), 256, 58880>>>(obs, benc);
    k2a_partial<<<dim3(16, 8), 256>>>();
    k3_stage2<<<dim3(128, 8), 256, 109568>>>(obs, bv_nb);   // 4th launch -> ncu capture
    k4a_partial<<<dim3(16, 32), 256>>>();
    k5_stats<<<dim3(16, 32), 256>>>();
    k6_scan<<<1, 256>>>(obs, out);
}

// round 15
// speedup vs baseline: 1.5257x; 1.5257x over previous
#include <cuda_runtime.h>
#include <cuda_bf16.h>
#include <math.h>
#include <float.h>

#define An    8
#define Bn    4096
#define FEATn 2560
#define SQRTD 11.3137085f

typedef unsigned long long u64;

// ------------- static device scratch (no allocation) -------------
__device__ __align__(16) float g_M1Pf[128 * 256];   // [kp][c*2+par] paired M1
__device__ __align__(16) float g_WencPf[32 * 512];  // [kp][c*2+par] paired Wenc
__device__ __align__(16) float g_M2P[128 * 128];    // [ep][hp*2+par]
__device__ __align__(16) float2 g_WvP[32 * 256];    // [kp][c]
__device__ float g_logit1[16 * Bn * 7];
__device__ float g_psum1[16 * 8];    // stage-1 mean partials
__device__ float g_lp[16 * Bn * 64];
__device__ float g_psum2[16 * 32];   // stage-2 mean partials
__device__ float g_pmax[16 * 32 * 64];
__device__ int   g_pargb[16 * 32 * 64];
__device__ float g_cargoT[(size_t)Bn * 2048];

__device__ __forceinline__ void ffma2(u64& acc, u64 x, u64 w) {
    asm("fma.rn.f32x2 %0, %1, %2, %0;" : "+l"(acc) : "l"(x), "l"(w));
}
__device__ __forceinline__ float2 unpack2(u64 v) {
    float2 f; asm("mov.b64 {%0, %1}, %2;" : "=f"(f.x), "=f"(f.y) : "l"(v)); return f;
}

// ---------------- K0: all prep, weight blocks FIRST, cargo after --------------
__global__ void k0_all(const float* __restrict__ obs,
                       const float* __restrict__ Wsel_nb, const float* __restrict__ Wk_nb,
                       const float* __restrict__ Wsel_poi, const float* __restrict__ Wk_poi,
                       const float* __restrict__ Wv, const float* __restrict__ Wenc) {
    __shared__ float T[32 * 65];
    int tid = threadIdx.x;
    if (blockIdx.x < 128) {
        int idx = blockIdx.x * 256 + tid;  // e(256) x ho(128)
        int e = idx >> 7, ho = idx & 127;
        int h = ho >> 6, o = ho & 63;
        const float* ws = Wsel_nb + h * 32768;
        const float* wk = Wk_nb + h * 8192;
        float s = 0.f;
        for (int d = 0; d < 128; d++) s += ws[d * 256 + e] * wk[d * 64 + o];
        g_M1Pf[(e >> 1) * 256 + ho * 2 + (e & 1)] = s;
        return;
    }
    if (blockIdx.x < 288) {
        int idx = (blockIdx.x - 128) * 256 + tid;
        if (idx < 16384) {
            int e = idx >> 6, hp = idx & 63;
            int h = hp >> 5, p = hp & 31;
            const float* ws = Wsel_poi + h * 32768;
            const float* wk = Wk_poi + h * 4096;
            float s = 0.f;
            for (int d = 0; d < 128; d++) s += ws[d * 256 + e] * wk[d * 32 + p];
            g_M2P[(e >> 1) * 128 + hp * 2 + (e & 1)] = s;
        } else if (idx < 24576) {
            int i3 = idx - 16384;
            int kp = i3 >> 8, c = i3 & 255;
            g_WvP[i3] = make_float2(Wv[c * 64 + 2 * kp], Wv[c * 64 + 2 * kp + 1]);
        } else {
            int i4 = idx - 24576;  // [kp(32)][c(256)][par(2)]
            int kp = i4 >> 9, rest = i4 & 511, c = rest >> 1, par = rest & 1;
            g_WencPf[i4] = Wenc[c * 64 + 2 * kp + par];
        }
        return;
    }
    int b = blockIdx.x - 288;
    const float4* in = (const float4*)(obs + (size_t)b * FEATn + 512);
    for (int i = tid; i < 512; i += 256) {
        float4 v = in[i];
        int c = i >> 3, p0 = (i & 7) * 4;
        T[(p0 + 0) * 65 + c] = v.x;
        T[(p0 + 1) * 65 + c] = v.y;
        T[(p0 + 2) * 65 + c] = v.z;
        T[(p0 + 3) * 65 + c] = v.w;
    }
    __syncthreads();
    float* ob = g_cargoT + (size_t)b * 2048;
    for (int i = tid; i < 2048; i += 256) ob[i] = T[(i >> 6) * 65 + (i & 63)];
}

// ---------------- K1: enc -> u -> stage-1 logits (shfl scheme, 32 rows) -------
__global__ __launch_bounds__(256, 2)
void k1_stage1(const float* __restrict__ obs, const float* __restrict__ benc) {
    extern __shared__ float F[];
    float* Fself = F;
    float* Fenc = F + 2176;
    float* Fu = F + 10496;
    const int a = blockIdx.y, b0 = blockIdx.x * 32, tid = threadIdx.x;
    const int lane = tid & 31;
    const int colT = tid & 63, rowT = tid >> 6;

    for (int i = tid; i < 512; i += 256) {
        int r = i >> 4, q4 = (i & 15) * 4;
        *(float4*)(Fself + r * 68 + q4) =
            *(const float4*)(obs + ((size_t)a * Bn + b0 + r) * FEATn + 448 + q4);
    }
    float breg[4];
#pragma unroll
    for (int c = 0; c < 4; c++) breg[c] = benc[colT * 4 + c];
    __syncthreads();

    {
        u64 acc2[8][4];
#pragma unroll
        for (int r = 0; r < 8; r++)
#pragma unroll
            for (int c = 0; c < 4; c++) acc2[r][c] = 0ull;
#pragma unroll 4
        for (int kp = 0; kp < 32; kp++) {
            u64 tmp = 0ull;
            if (lane < 8) tmp = *(const u64*)&Fself[(rowT * 8 + lane) * 68 + 2 * kp];
            ulonglong2 wA = *(const ulonglong2*)&g_WencPf[kp * 512 + colT * 8];
            ulonglong2 wB = *(const ulonglong2*)&g_WencPf[kp * 512 + colT * 8 + 4];
#pragma unroll
            for (int r = 0; r < 8; r++) {
                u64 xv = __shfl_sync(0xffffffffu, tmp, r);
                ffma2(acc2[r][0], xv, wA.x);
                ffma2(acc2[r][1], xv, wA.y);
                ffma2(acc2[r][2], xv, wB.x);
                ffma2(acc2[r][3], xv, wB.y);
            }
        }
#pragma unroll
        for (int r = 0; r < 8; r++)
#pragma unroll
            for (int c = 0; c < 4; c++) {
                float2 f = unpack2(acc2[r][c]);
                float v = f.x + f.y + breg[c];
                Fenc[(rowT * 8 + r) * 260 + colT * 4 + c] = (v >= 0.f) ? v : 0.01f * v;
            }
    }
    __syncthreads();

    {
        u64 uacc[8][2];
#pragma unroll
        for (int r = 0; r < 8; r++) { uacc[r][0] = 0ull; uacc[r][1] = 0ull; }
#pragma unroll 4
        for (int kp = 0; kp < 128; kp++) {
            u64 tmp = 0ull;
            if (lane < 8) tmp = *(const u64*)&Fenc[(rowT * 8 + lane) * 260 + 2 * kp];
            ulonglong2 m = *(const ulonglong2*)&g_M1Pf[kp * 256 + colT * 4];
#pragma unroll
            for (int r = 0; r < 8; r++) {
                u64 xv = __shfl_sync(0xffffffffu, tmp, r);
                ffma2(uacc[r][0], xv, m.x);
                ffma2(uacc[r][1], xv, m.y);
            }
        }
#pragma unroll
        for (int r = 0; r < 8; r++) {
            float2 fa = unpack2(uacc[r][0]), fb = unpack2(uacc[r][1]);
            Fu[(rowT * 8 + r) * 132 + colT * 2] = fa.x + fa.y;
            Fu[(rowT * 8 + r) * 132 + colT * 2 + 1] = fb.x + fb.y;
        }
    }
    __syncthreads();

    {
        int w = tid >> 5;
        for (int rr = 0; rr < 4; rr++) {
            int r = w * 4 + rr, b = b0 + r;
            float u0 = Fu[r * 132 + lane], u1 = Fu[r * 132 + 32 + lane];
            float u2 = Fu[r * 132 + 64 + lane], u3 = Fu[r * 132 + 96 + lane];
            const float* x = obs + ((size_t)a * Bn + b) * FEATn;
#pragma unroll
            for (int n = 0; n < 7; n++) {
                float xa = x[n * 64 + lane], xb = x[n * 64 + 32 + lane];
                float p0 = xa * u0 + xb * u1;
                float p1 = xa * u2 + xb * u3;
#pragma unroll
                for (int off = 16; off; off >>= 1) {
                    p0 += __shfl_xor_sync(0xffffffffu, p0, off);
                    p1 += __shfl_xor_sync(0xffffffffu, p1, off);
                }
                if (lane == 0) {
                    g_logit1[((size_t)a * Bn + b) * 7 + n] = p0 / SQRTD;
                    g_logit1[((size_t)(8 + a) * Bn + b) * 7 + n] = p1 / SQRTD;
                }
            }
        }
    }
}

// ---------------- K2a: stage-1 mean partials, grid (16,8) --------------------
__global__ void k2a_partial() {
    int pair = blockIdx.x, chunk = blockIdx.y;
    const float* p = g_logit1 + (size_t)pair * Bn * 7 + chunk * 3584;
    float s = 0.f;
    for (int i = threadIdx.x; i < 3584; i += 256) s += p[i];
    __shared__ float red[256];
    red[threadIdx.x] = s;
    __syncthreads();
    for (int st = 128; st; st >>= 1) {
        if (threadIdx.x < st) red[threadIdx.x] += red[threadIdx.x + st];
        __syncthreads();
    }
    if (threadIdx.x == 0) g_psum1[pair * 8 + chunk] = red[0];
}

// ---------------- K3: V-GEMM (shfl, reg accum, Fx reg-prefetch), t, lp -------
__global__ __launch_bounds__(256, 2)
void k3_stage2(const float* __restrict__ obs, const float* __restrict__ bv) {
    extern __shared__ float F[];
    float* Fwv = F;
    float* Fnbacc = F + 16384;
    float* Fx = F + 24704;
    float* Fw = F + 26880;
    float* Ft = Fx;
    const int a = blockIdx.y, b0 = blockIdx.x * 32, tid = threadIdx.x;
    const int lane = tid & 31;

    {
        const float4* src = (const float4*)g_WvP;
        float4* dst = (float4*)Fwv;
        for (int i = tid; i < 4096; i += 256) dst[i] = src[i];
    }
    if (tid < 64) {
        int r = tid >> 1, h2 = tid & 1, pair = h2 * 8 + a, b = b0 + r;
        float dn = 0.f;
#pragma unroll
        for (int j = 0; j < 8; j++) dn += g_psum1[pair * 8 + j];
        dn = dn / 28672.0f + 1e-9f;
        const float* lg = g_logit1 + ((size_t)pair * Bn + b) * 7;
        float L[7], m = -FLT_MAX, s = 0.f;
#pragma unroll
        for (int n = 0; n < 7; n++) { L[n] = lg[n] / dn; m = fmaxf(m, L[n]); }
#pragma unroll
        for (int n = 0; n < 7; n++) { L[n] = expf(L[n] - m); s += L[n]; }
#pragma unroll
        for (int n = 0; n < 7; n++) Fw[r * 16 + h2 * 8 + n] = L[n] / s;
    }

    const int colT = tid & 63, rowT = tid >> 6;
    const int h = (tid >> 5) & 1;
    float bvr[4];
#pragma unroll
    for (int c = 0; c < 4; c++) bvr[c] = bv[colT * 4 + c];

    float nbacc[8][4];
#pragma unroll
    for (int r = 0; r < 8; r++)
#pragma unroll
        for (int c = 0; c < 4; c++) nbacc[r][c] = 0.f;

    // register prefetch of Fx tiles: thread covers float4 indices tid, tid+256
    const int pr0 = tid >> 4, pq0 = (tid & 15) * 4;
    const int pr1 = (tid + 256) >> 4, pq1 = ((tid + 256) & 15) * 4;
    float4 pre0 = *(const float4*)(obs + ((size_t)a * Bn + b0 + pr0) * FEATn + pq0);
    float4 pre1 = *(const float4*)(obs + ((size_t)a * Bn + b0 + pr1) * FEATn + pq1);

    for (int n = 0; n < 7; n++) {
        __syncthreads();  // previous tile consumers done
        *(float4*)(Fx + pr0 * 68 + pq0) = pre0;
        *(float4*)(Fx + pr1 * 68 + pq1) = pre1;
        if (n < 6) {  // issue next tile loads; latency overlaps compute below
            pre0 = *(const float4*)(obs + ((size_t)a * Bn + b0 + pr0) * FEATn + (n + 1) * 64 + pq0);
            pre1 = *(const float4*)(obs + ((size_t)a * Bn + b0 + pr1) * FEATn + (n + 1) * 64 + pq1);
        }
        __syncthreads();  // tile n visible

        u64 acc2[8][4];
#pragma unroll
        for (int r = 0; r < 8; r++)
#pragma unroll
            for (int c = 0; c < 4; c++) acc2[r][c] = 0ull;

#pragma unroll 4
        for (int kp = 0; kp < 32; kp++) {
            u64 tmp = 0ull;
            if (lane < 8) tmp = *(const u64*)&Fx[(rowT * 8 + lane) * 68 + 2 * kp];
            ulonglong2 wA = *(const ulonglong2*)&Fwv[kp * 512 + colT * 8];
            ulonglong2 wB = *(const ulonglong2*)&Fwv[kp * 512 + colT * 8 + 4];
#pragma unroll
            for (int r = 0; r < 8; r++) {
                u64 xv = __shfl_sync(0xffffffffu, tmp, r);
                ffma2(acc2[r][0], xv, wA.x);
                ffma2(acc2[r][1], xv, wA.y);
                ffma2(acc2[r][2], xv, wB.x);
                ffma2(acc2[r][3], xv, wB.y);
            }
        }
#pragma unroll
        for (int r = 0; r < 8; r++) {
            float wr = Fw[(rowT * 8 + r) * 16 + h * 8 + n];
            float2 f0 = unpack2(acc2[r][0]), f1 = unpack2(acc2[r][1]);
            float2 f2 = unpack2(acc2[r][2]), f3 = unpack2(acc2[r][3]);
            float v0 = f0.x + f0.y + bvr[0]; v0 = (v0 >= 0.f) ? v0 : 0.01f * v0;
            float v1 = f1.x + f1.y + bvr[1]; v1 = (v1 >= 0.f) ? v1 : 0.01f * v1;
            float v2 = f2.x + f2.y + bvr[2]; v2 = (v2 >= 0.f) ? v2 : 0.01f * v2;
            float v3 = f3.x + f3.y + bvr[3]; v3 = (v3 >= 0.f) ? v3 : 0.01f * v3;
            nbacc[r][0] += wr * v0; nbacc[r][1] += wr * v1;
            nbacc[r][2] += wr * v2; nbacc[r][3] += wr * v3;
        }
    }
    __syncthreads();
#pragma unroll
    for (int r = 0; r < 8; r++)
        *(float4*)&Fnbacc[(rowT * 8 + r) * 260 + colT * 4] =
            make_float4(nbacc[r][0], nbacc[r][1], nbacc[r][2], nbacc[r][3]);
    __syncthreads();

    {
        const int colTt = tid & 31, rowTt = tid >> 5;
        u64 tacc[4][2];
#pragma unroll
        for (int r = 0; r < 4; r++) { tacc[r][0] = 0ull; tacc[r][1] = 0ull; }
#pragma unroll 4
        for (int ep = 0; ep < 128; ep++) {
            u64 tmp = 0ull;
            if (lane < 4) tmp = *(const u64*)&Fnbacc[(rowTt * 4 + lane) * 260 + 2 * ep];
            ulonglong2 m2 = *(const ulonglong2*)&g_M2P[ep * 128 + colTt * 4];
#pragma unroll
            for (int r = 0; r < 4; r++) {
                u64 xv = __shfl_sync(0xffffffffu, tmp, r);
                ffma2(tacc[r][0], xv, m2.x);
                ffma2(tacc[r][1], xv, m2.y);
            }
        }
        __syncthreads();  // Ft aliases Fx
#pragma unroll
        for (int r = 0; r < 4; r++) {
            float2 fa = unpack2(tacc[r][0]), fb = unpack2(tacc[r][1]);
            Ft[(rowTt * 4 + r) * 64 + colTt * 2] = (fa.x + fa.y) * (1.0f / SQRTD);
            Ft[(rowTt * 4 + r) * 64 + colTt * 2 + 1] = (fb.x + fb.y) * (1.0f / SQRTD);
        }
    }
    __syncthreads();

    {
        int w8 = tid >> 5;
        for (int rr = 0; rr < 4; rr++) {
            int r = w8 * 4 + rr, b = b0 + r;
            const float* ct = g_cargoT + (size_t)b * 2048;
#pragma unroll
            for (int ch = 0; ch < 2; ch++) {
                float acc0 = 0.f, acc1 = 0.f;
#pragma unroll
                for (int p = 0; p < 32; p++) {
                    float x = ct[p * 64 + ch * 32 + lane];
                    acc0 = fmaf(Ft[r * 64 + p], x, acc0);
                    acc1 = fmaf(Ft[r * 64 + 32 + p], x, acc1);
                }
                g_lp[((size_t)a * Bn + b) * 64 + ch * 32 + lane] = acc0;
                g_lp[((size_t)(8 + a) * Bn + b) * 64 + ch * 32 + lane] = acc1;
            }
        }
    }
}

// ---------------- K4a: stage-2 mean partials, grid (16,32) --------------------
__global__ void k4a_partial() {
    int pair = blockIdx.x, chunk = blockIdx.y;
    const float* p = g_lp + (size_t)pair * Bn * 64 + chunk * 8192;
    float s = 0.f;
    for (int i = threadIdx.x; i < 8192; i += 256) s += p[i];
    __shared__ float red[256];
    red[threadIdx.x] = s;
    __syncthreads();
    for (int st = 128; st; st >>= 1) {
        if (threadIdx.x < st) red[threadIdx.x] += red[threadIdx.x + st];
        __syncthreads();
    }
    if (threadIdx.x == 0) g_psum2[pair * 32 + chunk] = red[0];
}

// ---------------- K5: fused softmax + column (max, first-b) stats ------------
__global__ void k5_stats() {
    int pair = blockIdx.x, chunk = blockIdx.y;
    int w = threadIdx.x >> 5, lane = threadIdx.x & 31;
    float d = 0.f;
#pragma unroll
    for (int j = 0; j < 32; j++) d += g_psum2[pair * 32 + j];
    d = d / 262144.0f + 1e-9f;
    float m0 = -FLT_MAX, m1 = -FLT_MAX;
    int a0 = 1 << 30, a1 = 1 << 30;
    int brow0 = chunk * 128 + w * 16;
    for (int i = 0; i < 16; i++) {
        int b = brow0 + i;
        const float* p = g_lp + ((size_t)pair * Bn + b) * 64;
        float L0 = p[lane] / d, L1 = p[lane + 32] / d;
        float mx = fmaxf(L0, L1);
#pragma unroll
        for (int off = 16; off; off >>= 1) mx = fmaxf(mx, __shfl_xor_sync(0xffffffffu, mx, off));
        float e0 = expf(L0 - mx), e1 = expf(L1 - mx);
        float s = e0 + e1;
#pragma unroll
        for (int off = 16; off; off >>= 1) s += __shfl_xor_sync(0xffffffffu, s, off);
        float inv = 1.0f / s;
        float w0 = e0 * inv, w1 = e1 * inv;
        if (w0 > m0) { m0 = w0; a0 = b; }
        if (w1 > m1) { m1 = w1; a1 = b; }
    }
    __shared__ float sv[8 * 64];
    __shared__ int sb[8 * 64];
    sv[w * 64 + lane] = m0;        sb[w * 64 + lane] = a0;
    sv[w * 64 + lane + 32] = m1;   sb[w * 64 + lane + 32] = a1;
    __syncthreads();
    if (threadIdx.x < 64) {
        int c = threadIdx.x;
        float bvv = sv[c];
        int bbb = sb[c];
        for (int j = 1; j < 8; j++) {
            float v2 = sv[j * 64 + c];
            int b2 = sb[j * 64 + c];
            if (v2 > bvv || (v2 == bvv && b2 < bbb)) { bvv = v2; bbb = b2; }
        }
        g_pmax[(pair * 32 + chunk) * 64 + c] = bvv;
        g_pargb[(pair * 32 + chunk) * 64 + c] = bbb;
    }
}

// ---------------- K6: merge stats, 16-step scan, broadcast output ------------
__global__ void k6_scan(const float* __restrict__ obs, float* __restrict__ out) {
    __shared__ float smax[1024];
    __shared__ int sab[1024];
    __shared__ int smask[64];
    __shared__ float sci[8];
    int tid = threadIdx.x;
    for (int i = tid; i < 1024; i += 256) {
        int pair = i >> 6, c = i & 63;
        float bvv = -FLT_MAX;
        int bbb = 1 << 30;
        for (int j = 0; j < 32; j++) {
            float v = g_pmax[(pair * 32 + j) * 64 + c];
            int b2 = g_pargb[(pair * 32 + j) * 64 + c];
            if (v > bvv || (v == bvv && b2 < bbb)) { bvv = v; bbb = b2; }
        }
        smax[i] = bvv;
        sab[i] = bbb;
    }
    if (tid < 64) {
        int off = (32 * tid + 2047) & 2047;
        smask[tid] = (obs[512 + off] == 1.0f) ? 1 : 0;
    }
    __syncthreads();
    if (tid == 0) {
        for (int i = 0; i < 16; i++) {
            float bestv = -FLT_MAX;
            int bestflat = -1;
            for (int c = 0; c < 64; c++) {
                if (smask[c]) continue;
                float v = smax[i * 64 + c];
                int flat = sab[i * 64 + c] * 64 + c;
                if (bestflat < 0 || v > bestv || (v == bestv && flat < bestflat)) {
                    bestv = v;
                    bestflat = flat;
                }
            }
            int ci = (bestflat < 0) ? 0 : bestflat;
            if (ci < 64) smask[ci] = 1;
            if (i >= 8) sci[i - 8] = (float)ci;
        }
    }
    __syncthreads();
    for (int i = tid; i < 32768; i += 256) out[i] = sci[i >> 12];
}

extern "C" void kernel_launch(void* const* d_in, const int* in_sizes, int n_in,
                              void* d_out, int out_size) {
    const float* obs = (const float*)d_in[0];
    const float* Wenc = (const float*)d_in[1];
    const float* benc = (const float*)d_in[2];
    const float* Wk_nb = (const float*)d_in[3];
    const float* Wsel_nb = (const float*)d_in[4];
    const float* Wv_nb = (const float*)d_in[5];
    const float* bv_nb = (const float*)d_in[6];
    const float* Wk_poi = (const float*)d_in[7];
    const float* Wsel_poi = (const float*)d_in[8];
    float* out = (float*)d_out;

    cudaFuncSetAttribute(k1_stage1, cudaFuncAttributeMaxDynamicSharedMemorySize, 58880);
    cudaFuncSetAttribute(k3_stage2, cudaFuncAttributeMaxDynamicSharedMemorySize, 109568);

    k0_all<<<4384, 256>>>(obs, Wsel_nb, Wk_nb, Wsel_poi, Wk_poi, Wv_nb, Wenc);
    k1_stage1<<<dim3(128, 8), 256, 58880>>>(obs, benc);
    k2a_partial<<<dim3(16, 8), 256>>>();
    k3_stage2<<<dim3(128, 8), 256, 109568>>>(obs, bv_nb);   // 4th launch -> ncu capture
    k4a_partial<<<dim3(16, 32), 256>>>();
    k5_stats<<<dim3(16, 32), 256>>>();
    k6_scan<<<1, 256>>>(obs, out);
}